// round 13
// baseline (speedup 1.0000x reference)
#include <cuda_runtime.h>
#include <cstdint>

// ForgetMult: h_t = f_t*x_t + (1-f_t)*h_{t-1}
// f,x: (4096, 16, 512) fp32. out inclusive, h_0 = hidden_init.
//
// Single-pass chunked scan, float4 channels, SMEM-STAGED single read:
//   f,x are cp.async'd (LDGSTS, register-free MLP) into smem ONCE; both the
//   composite fold and the final replay read from smem. This removes the
//   256MB phase-4 L2 re-read of the previous scheme, cutting LTS traffic
//   ~1.02GB -> ~768MB (the measured LTS cap is what pinned all previous
//   variants at ~88us kernel time).
//   Geometry: TB=128 timesteps x TILE_C4=16 f4-channels per block
//   (slab 64KB + 8KB scan = 72KB smem) -> 3 blocks/SM, 24 warps/SM.
//   Look-back depth <= 31, waited lane-parallel by warp 0.

#define SEQ_LEN  4096
#define C4       2048                  // float4 channels
#define SL       8                     // timesteps per thread
#define SUBS     16                    // sub-chunks per block
#define TILE_C4  16                    // f4 channels per block (64 fp32)
#define TB       (SL * SUBS)           // 128 timesteps per block
#define TBLKS    (SEQ_LEN / TB)        // 32
#define TILES    (C4 / TILE_C4)        // 128
#define NTHREADS (TILE_C4 * SUBS)      // 256

#define SMEM_BYTES ((2 * TB * TILE_C4 + 2 * SUBS * TILE_C4 + TILE_C4) * 16)

__device__ float4 g_aggA[TBLKS * C4];
__device__ float4 g_aggB[TBLKS * C4];
__device__ float4 g_prefH[C4];            // h at end of time-block 0
__device__ int    g_flag[TILES * TBLKS];  // [tile][tblk]; 0=none 1=agg 2=prefix

__device__ __forceinline__ float4 f4_fma(float4 a, float4 h, float4 b) {
    return make_float4(fmaf(a.x, h.x, b.x), fmaf(a.y, h.y, b.y),
                       fmaf(a.z, h.z, b.z), fmaf(a.w, h.w, b.w));
}
__device__ __forceinline__ float4 f4_mul(float4 a, float4 b) {
    return make_float4(a.x * b.x, a.y * b.y, a.z * b.z, a.w * b.w);
}
__device__ __forceinline__ int ld_acquire_gpu(const int* p) {
    int v;
    asm volatile("ld.acquire.gpu.global.b32 %0, [%1];" : "=r"(v) : "l"(p) : "memory");
    return v;
}
__device__ __forceinline__ void st_release_gpu(int* p, int v) {
    asm volatile("st.release.gpu.global.b32 [%0], %1;" :: "l"(p), "r"(v) : "memory");
}
__device__ __forceinline__ void cp_async16(uint32_t dst_smem, const void* src) {
    asm volatile("cp.async.ca.shared.global [%0], [%1], 16;"
                 :: "r"(dst_smem), "l"(src) : "memory");
}

__global__ void reset_flags_kernel()
{
    int i = blockIdx.x * blockDim.x + threadIdx.x;
    if (i < TILES * TBLKS) g_flag[i] = 0;
}

__global__ __launch_bounds__(NTHREADS, 3)
void forget_mult_v12_kernel(
    const float4* __restrict__ f,
    const float4* __restrict__ x,
    const float4* __restrict__ h0,
    float4* __restrict__ out)
{
    extern __shared__ float4 smem[];
    float4* sF   = smem;                              // [TB][TILE_C4]
    float4* sX   = sF + TB * TILE_C4;                 // [TB][TILE_C4]
    float4* sA   = sX + TB * TILE_C4;                 // [SUBS][TILE_C4]
    float4* sB   = sA + SUBS * TILE_C4;               // [SUBS][TILE_C4]
    float4* sHin = sB + SUBS * TILE_C4;               // [TILE_C4]

    const int tid  = threadIdx.x;
    const int c    = tid & (TILE_C4 - 1);       // f4 channel within tile
    const int s    = tid >> 4;                  // sub-chunk index (0..15)
    const int tile = blockIdx.x >> 5;           // / TBLKS
    const int tblk = blockIdx.x & (TBLKS - 1);  // fastest-varying in bid

    const int cg = tile * TILE_C4 + c;
    const int t0 = tblk * TB + s * SL;

    const float4* fp = f + (size_t)t0 * C4 + cg;
    const float4* xp = x + (size_t)t0 * C4 + cg;

    // ---- Phase 0: cp.async the whole slab into smem (register-free MLP) ----
    uint32_t sF_u, sX_u;
    {
        uint32_t base;
        asm("{ .reg .u64 t; cvta.to.shared.u64 t, %1; cvt.u32.u64 %0, t; }"
            : "=r"(base) : "l"(smem));
        const uint32_t row0 = (uint32_t)((s * SL) * TILE_C4 + c) * 16u;
        sF_u = base + row0;
        sX_u = base + (uint32_t)(TB * TILE_C4) * 16u + row0;
    }
#pragma unroll
    for (int i = 0; i < SL; i++) {
        cp_async16(sF_u + (uint32_t)i * TILE_C4 * 16u, fp + (size_t)i * C4);
        cp_async16(sX_u + (uint32_t)i * TILE_C4 * 16u, xp + (size_t)i * C4);
    }
    asm volatile("cp.async.commit_group;" ::: "memory");
    asm volatile("cp.async.wait_group 0;" ::: "memory");
    __syncthreads();

    // ---- Phase 1: fold sub-chunk composite from smem ----
    float4 cA = make_float4(1.f, 1.f, 1.f, 1.f);
    float4 cB = make_float4(0.f, 0.f, 0.f, 0.f);
#pragma unroll
    for (int i = 0; i < SL; i++) {
        float4 ft = sF[(s * SL + i) * TILE_C4 + c];
        float4 xt = sX[(s * SL + i) * TILE_C4 + c];
        float4 a = make_float4(1.f - ft.x, 1.f - ft.y, 1.f - ft.z, 1.f - ft.w);
        float4 b = f4_mul(ft, xt);
        cB = f4_fma(a, cB, b);
        cA = f4_mul(cA, a);
    }

    // ---- Phase 2: Hillis-Steele over the 16 sub-chunks ----
    sA[s * TILE_C4 + c] = cA;
    sB[s * TILE_C4 + c] = cB;
    __syncthreads();
#pragma unroll
    for (int d = 1; d < SUBS; d <<= 1) {
        float4 pA, pB;
        if (s >= d) {
            pA = sA[(s - d) * TILE_C4 + c];
            pB = sB[(s - d) * TILE_C4 + c];
        }
        __syncthreads();
        if (s >= d) {
            cB = f4_fma(cA, pB, cB);   // cur ∘ prev
            cA = f4_mul(cA, pA);
            sA[s * TILE_C4 + c] = cA;
            sB[s * TILE_C4 + c] = cB;
        }
        __syncthreads();
    }
    float4 exA = make_float4(1.f, 1.f, 1.f, 1.f);
    float4 exB = make_float4(0.f, 0.f, 0.f, 0.f);
    if (s > 0) {
        exA = sA[(s - 1) * TILE_C4 + c];
        exB = sB[(s - 1) * TILE_C4 + c];
    }

    // ---- Phase 3: look-back; warp 0 waits lane-parallel (32 lanes),
    //      lanes 0..15 publish/fold their channel ----
    if (tid < 32) {
        const int lane = tid;
        float4 blkA, blkB;
        int cg0 = 0;
        if (lane < TILE_C4) {
            blkA = sA[(SUBS - 1) * TILE_C4 + lane];
            blkB = sB[(SUBS - 1) * TILE_C4 + lane];
            cg0  = tile * TILE_C4 + lane;
        }
        const int fbase = tile * TBLKS;
        if (tblk == 0) {
            if (lane < TILE_C4) {
                float4 hin0 = h0[cg0];
                g_prefH[cg0] = f4_fma(blkA, hin0, blkB);
                sHin[lane] = hin0;
            }
            __syncwarp(0xFFFFFFFFu);
            if (lane == 0)
                st_release_gpu(&g_flag[fbase + 0], 2);
        } else {
            if (lane < TILE_C4) {
                g_aggA[(size_t)tblk * C4 + cg0] = blkA;
                g_aggB[(size_t)tblk * C4 + cg0] = blkB;
            }
            __syncwarp(0xFFFFFFFFu);
            if (lane == 0)
                st_release_gpu(&g_flag[fbase + tblk], 1);

            // Parallel wait: lane j polls predecessor j (tblk <= 31).
            {
                const int need = (lane == 0) ? 2 : 1;
                bool ok;
                do {
                    ok = (lane >= tblk) ||
                         (ld_acquire_gpu(&g_flag[fbase + lane]) >= need);
                } while (!__all_sync(0xFFFFFFFFu, ok));
            }
            __syncwarp(0xFFFFFFFFu);   // order acquires before cross-lane reads

            if (lane < TILE_C4) {
                float4 accA = make_float4(1.f, 1.f, 1.f, 1.f);
                float4 accB = make_float4(0.f, 0.f, 0.f, 0.f);
#pragma unroll 4
                for (int j = tblk - 1; j >= 1; j--) {
                    float4 aj = g_aggA[(size_t)j * C4 + cg0];
                    float4 bj = g_aggB[(size_t)j * C4 + cg0];
                    accB = f4_fma(accA, bj, accB);
                    accA = f4_mul(accA, aj);
                }
                float4 hpre = g_prefH[cg0];
                sHin[lane] = f4_fma(accA, hpre, accB);
            }
        }
    }
    __syncthreads();

    // ---- Phase 4: replay from SMEM (no global re-read), store out ----
    float4 h = f4_fma(exA, sHin[c], exB);
    float4* op = out + (size_t)t0 * C4 + cg;
#pragma unroll
    for (int i = 0; i < SL; i++) {
        float4 ft = sF[(s * SL + i) * TILE_C4 + c];
        float4 xt = sX[(s * SL + i) * TILE_C4 + c];
        float4 a = make_float4(1.f - ft.x, 1.f - ft.y, 1.f - ft.z, 1.f - ft.w);
        float4 b = f4_mul(ft, xt);
        h = f4_fma(a, h, b);
        __stcs(op + (size_t)i * C4, h);
    }
}

extern "C" void kernel_launch(void* const* d_in, const int* in_sizes, int n_in,
                              void* d_out, int out_size)
{
    const float4* f  = (const float4*)d_in[0];
    const float4* x  = (const float4*)d_in[1];
    const float4* h0 = (const float4*)d_in[2];
    float4* out = (float4*)d_out;

    static bool attr_set = false;
    if (!attr_set) {
        cudaFuncSetAttribute(forget_mult_v12_kernel,
                             cudaFuncAttributeMaxDynamicSharedMemorySize,
                             SMEM_BYTES);
        attr_set = true;
    }

    reset_flags_kernel<<<(TILES * TBLKS + 255) / 256, 256>>>();

    dim3 grid(TILES * TBLKS);   // tblk fastest -> predecessors at lower bid
    dim3 block(NTHREADS);
    forget_mult_v12_kernel<<<grid, block, SMEM_BYTES>>>(f, x, h0, out);
}

// round 14
// speedup vs baseline: 1.0206x; 1.0206x over previous
#include <cuda_runtime.h>

// ForgetMult: h_t = f_t*x_t + (1-f_t)*h_{t-1}
// f,x: (4096, 16, 512) fp32. out inclusive, h_0 = hidden_init.
//
// Single-pass chunked scan, float4 channels, REGISTER-staged prefix:
//   Phase 1 loads f,x ONCE and folds the within-sub-chunk INCLUSIVE prefix
//   (A_i,B_i) in place in registers. Phase 4 is then h_i = fma(A_i,h_sub,B_i)
//   + store: no global re-read (saves 256MB of LTS traffic vs the L2-re-read
//   scheme; LTS was the binding cap at ~6300 B/cyc) and no serial chain.
//   Geometry: 256 thr = 16 f4-ch x 16 sub-chunks x SL=8 steps -> TB=128,
//   TBLKS=32. 2 blocks/SM (reg-limited). Look-back depth <= 31 handled by
//   the lane-parallel ballot wait (warp 0, 32 lanes).

#define SEQ_LEN  4096
#define C4       2048                  // float4 channels
#define SL       8                     // timesteps per thread
#define SUBS     16                    // sub-chunks per block
#define TILE_C4  16                    // f4 channels per block (64 fp32)
#define TB       (SL * SUBS)           // 128 timesteps per block
#define TBLKS    (SEQ_LEN / TB)        // 32
#define TILES    (C4 / TILE_C4)        // 128
#define NTHREADS (TILE_C4 * SUBS)      // 256

__device__ float4 g_aggA[TBLKS * C4];
__device__ float4 g_aggB[TBLKS * C4];
__device__ float4 g_prefH[C4];            // h at end of time-block 0
__device__ int    g_flag[TILES * TBLKS];  // [tile][tblk]; 0=none 1=agg 2=prefix

__device__ __forceinline__ float4 f4_fma(float4 a, float4 h, float4 b) {
    return make_float4(fmaf(a.x, h.x, b.x), fmaf(a.y, h.y, b.y),
                       fmaf(a.z, h.z, b.z), fmaf(a.w, h.w, b.w));
}
__device__ __forceinline__ float4 f4_mul(float4 a, float4 b) {
    return make_float4(a.x * b.x, a.y * b.y, a.z * b.z, a.w * b.w);
}
__device__ __forceinline__ int ld_acquire_gpu(const int* p) {
    int v;
    asm volatile("ld.acquire.gpu.global.b32 %0, [%1];" : "=r"(v) : "l"(p) : "memory");
    return v;
}
__device__ __forceinline__ void st_release_gpu(int* p, int v) {
    asm volatile("st.release.gpu.global.b32 [%0], %1;" :: "l"(p), "r"(v) : "memory");
}

__global__ void reset_flags_kernel()
{
    int i = blockIdx.x * blockDim.x + threadIdx.x;
    if (i < TILES * TBLKS) g_flag[i] = 0;
}

__global__ __launch_bounds__(NTHREADS, 2)
void forget_mult_v13_kernel(
    const float4* __restrict__ f,
    const float4* __restrict__ x,
    const float4* __restrict__ h0,
    float4* __restrict__ out)
{
    __shared__ float4 sA[SUBS * TILE_C4];
    __shared__ float4 sB[SUBS * TILE_C4];
    __shared__ float4 sHin[TILE_C4];

    const int tid  = threadIdx.x;
    const int c    = tid & (TILE_C4 - 1);       // f4 channel within tile
    const int s    = tid >> 4;                  // sub-chunk index (0..15)
    const int tile = blockIdx.x >> 5;           // / TBLKS
    const int tblk = blockIdx.x & (TBLKS - 1);  // fastest-varying in bid

    const int cg = tile * TILE_C4 + c;
    const int t0 = tblk * TB + s * SL;

    const float4* fp = f + (size_t)t0 * C4 + cg;
    const float4* xp = x + (size_t)t0 * C4 + cg;

    // ---- Phase 1: load once, fold INCLUSIVE prefix in place (registers) ----
    // rA[i], rB[i] become (A_i, B_i): h_{t0+i} = B_i + A_i * h_in(sub-chunk).
    float4 rA[SL], rB[SL];
#pragma unroll
    for (int i = 0; i < SL; i++) {
        float4 ft = __ldcs(fp + (size_t)i * C4);   // single read: evict-first
        float4 xt = __ldcs(xp + (size_t)i * C4);
        rA[i] = make_float4(1.f - ft.x, 1.f - ft.y, 1.f - ft.z, 1.f - ft.w);
        rB[i] = f4_mul(ft, xt);
    }
#pragma unroll
    for (int i = 1; i < SL; i++) {
        rB[i] = f4_fma(rA[i], rB[i - 1], rB[i]);   // B_i = a_i*B_{i-1} + b_i
        rA[i] = f4_mul(rA[i], rA[i - 1]);          // A_i = a_i*A_{i-1}
    }
    float4 cA = rA[SL - 1], cB = rB[SL - 1];       // sub-chunk composite

    // ---- Phase 2: Hillis-Steele over the 16 sub-chunks ----
    sA[s * TILE_C4 + c] = cA;
    sB[s * TILE_C4 + c] = cB;
    __syncthreads();
#pragma unroll
    for (int d = 1; d < SUBS; d <<= 1) {
        float4 pA, pB;
        if (s >= d) {
            pA = sA[(s - d) * TILE_C4 + c];
            pB = sB[(s - d) * TILE_C4 + c];
        }
        __syncthreads();
        if (s >= d) {
            cB = f4_fma(cA, pB, cB);   // cur ∘ prev
            cA = f4_mul(cA, pA);
            sA[s * TILE_C4 + c] = cA;
            sB[s * TILE_C4 + c] = cB;
        }
        __syncthreads();
    }
    float4 exA = make_float4(1.f, 1.f, 1.f, 1.f);
    float4 exB = make_float4(0.f, 0.f, 0.f, 0.f);
    if (s > 0) {
        exA = sA[(s - 1) * TILE_C4 + c];
        exB = sB[(s - 1) * TILE_C4 + c];
    }

    // ---- Phase 3: look-back; warp 0 lane-parallel wait (tblk <= 31) ----
    if (tid < 32) {
        const int lane = tid;
        float4 blkA, blkB;
        int cg0 = 0;
        if (lane < TILE_C4) {
            blkA = sA[(SUBS - 1) * TILE_C4 + lane];
            blkB = sB[(SUBS - 1) * TILE_C4 + lane];
            cg0  = tile * TILE_C4 + lane;
        }
        const int fbase = tile * TBLKS;
        if (tblk == 0) {
            if (lane < TILE_C4) {
                float4 hin0 = h0[cg0];
                g_prefH[cg0] = f4_fma(blkA, hin0, blkB);
                sHin[lane] = hin0;
            }
            __syncwarp(0xFFFFFFFFu);
            if (lane == 0)
                st_release_gpu(&g_flag[fbase + 0], 2);
        } else {
            if (lane < TILE_C4) {
                g_aggA[(size_t)tblk * C4 + cg0] = blkA;
                g_aggB[(size_t)tblk * C4 + cg0] = blkB;
            }
            __syncwarp(0xFFFFFFFFu);
            if (lane == 0)
                st_release_gpu(&g_flag[fbase + tblk], 1);

            // Parallel wait: lane j polls predecessor j; ballot collapses
            // all polls into ~1 L2 round-trip per retry.
            {
                const int need = (lane == 0) ? 2 : 1;
                bool ok;
                do {
                    ok = (lane >= tblk) ||
                         (ld_acquire_gpu(&g_flag[fbase + lane]) >= need);
                } while (!__all_sync(0xFFFFFFFFu, ok));
            }
            __syncwarp(0xFFFFFFFFu);   // order acquires before cross-lane reads

            if (lane < TILE_C4) {
                // Fold independent aggregate loads (HW-overlapped).
                float4 accA = make_float4(1.f, 1.f, 1.f, 1.f);
                float4 accB = make_float4(0.f, 0.f, 0.f, 0.f);
#pragma unroll 4
                for (int j = tblk - 1; j >= 1; j--) {
                    float4 aj = g_aggA[(size_t)j * C4 + cg0];
                    float4 bj = g_aggB[(size_t)j * C4 + cg0];
                    accB = f4_fma(accA, bj, accB);
                    accA = f4_mul(accA, aj);
                }
                float4 hpre = g_prefH[cg0];
                sHin[lane] = f4_fma(accA, hpre, accB);
            }
        }
    }
    __syncthreads();

    // ---- Phase 4: apply prefix from registers -- no re-read, no chain ----
    const float4 hsub = f4_fma(exA, sHin[c], exB);  // h entering sub-chunk
    float4* op = out + (size_t)t0 * C4 + cg;
#pragma unroll
    for (int i = 0; i < SL; i++) {
        float4 h = f4_fma(rA[i], hsub, rB[i]);      // independent per i
        __stcs(op + (size_t)i * C4, h);
    }
}

extern "C" void kernel_launch(void* const* d_in, const int* in_sizes, int n_in,
                              void* d_out, int out_size)
{
    const float4* f  = (const float4*)d_in[0];
    const float4* x  = (const float4*)d_in[1];
    const float4* h0 = (const float4*)d_in[2];
    float4* out = (float4*)d_out;

    reset_flags_kernel<<<(TILES * TBLKS + 255) / 256, 256>>>();

    dim3 grid(TILES * TBLKS);   // tblk fastest -> predecessors at lower bid
    dim3 block(NTHREADS);
    forget_mult_v13_kernel<<<grid, block>>>(f, x, h0, out);
}

// round 15
// speedup vs baseline: 1.1323x; 1.1094x over previous
#include <cuda_runtime.h>
#include <cstdint>

// ForgetMult: h_t = f_t*x_t + (1-f_t)*h_{t-1}
// f,x: (4096, 16, 512) fp32. out inclusive, h_0 = hidden_init.
//
// Single-pass chunked scan, float4 channels, SMEM-staged inclusive prefix:
//   Phase 0/1: cp.async.cg fills the (f,x) slab in per-timestep groups; the
//   fold consumes each group as it lands (wait_group SL-1-i) and OVERWRITES
//   the slab in place with the within-sub-chunk inclusive prefix (A_i,B_i).
//   Phase 4 is then pure LDS -> fma -> STG (no global re-read, no recompute,
//   per-thread-only smem slots). LTS traffic drops 1.02GB -> 768MB (LTS at
//   ~6300 B/cyc was the measured cap pinning the re-read design at ~88us).
//   Geometry: 256 thr = 16 f4-ch x 16 sub-chunks x SL=8 -> TB=128, TBLKS=32,
//   74KB smem -> 3 blocks/SM (24 warps). Look-back <= 31, lane-parallel.

#define SEQ_LEN  4096
#define C4       2048                  // float4 channels
#define SL       8                     // timesteps per thread
#define SUBS     16                    // sub-chunks per block
#define TILE_C4  16                    // f4 channels per block (64 fp32)
#define TB       (SL * SUBS)           // 128 timesteps per block
#define TBLKS    (SEQ_LEN / TB)        // 32
#define TILES    (C4 / TILE_C4)        // 128
#define NTHREADS (TILE_C4 * SUBS)      // 256

#define SLAB_F4   (TB * TILE_C4)       // 2048 float4 per array
#define SMEM_F4   (2 * SLAB_F4 + 2 * SUBS * TILE_C4 + TILE_C4)
#define SMEM_BYTES (SMEM_F4 * 16)      // 73,984 B -> 3 blocks/SM

__device__ float4 g_aggA[TBLKS * C4];
__device__ float4 g_aggB[TBLKS * C4];
__device__ float4 g_prefH[C4];            // h at end of time-block 0
__device__ int    g_flag[TILES * TBLKS];  // [tile][tblk]; 0=none 1=agg 2=prefix

__device__ __forceinline__ float4 f4_fma(float4 a, float4 h, float4 b) {
    return make_float4(fmaf(a.x, h.x, b.x), fmaf(a.y, h.y, b.y),
                       fmaf(a.z, h.z, b.z), fmaf(a.w, h.w, b.w));
}
__device__ __forceinline__ float4 f4_mul(float4 a, float4 b) {
    return make_float4(a.x * b.x, a.y * b.y, a.z * b.z, a.w * b.w);
}
__device__ __forceinline__ int ld_acquire_gpu(const int* p) {
    int v;
    asm volatile("ld.acquire.gpu.global.b32 %0, [%1];" : "=r"(v) : "l"(p) : "memory");
    return v;
}
__device__ __forceinline__ void st_release_gpu(int* p, int v) {
    asm volatile("st.release.gpu.global.b32 [%0], %1;" :: "l"(p), "r"(v) : "memory");
}
__device__ __forceinline__ void cp_async16(uint32_t dst_smem, const void* src) {
    asm volatile("cp.async.cg.shared.global [%0], [%1], 16;"
                 :: "r"(dst_smem), "l"(src) : "memory");
}
template <int N>
__device__ __forceinline__ void cp_async_wait() {
    asm volatile("cp.async.wait_group %0;" :: "n"(N) : "memory");
}

__global__ void reset_flags_kernel()
{
    int i = blockIdx.x * blockDim.x + threadIdx.x;
    if (i < TILES * TBLKS) g_flag[i] = 0;
}

__global__ __launch_bounds__(NTHREADS, 3)
void forget_mult_v14_kernel(
    const float4* __restrict__ f,
    const float4* __restrict__ x,
    const float4* __restrict__ h0,
    float4* __restrict__ out)
{
    extern __shared__ float4 smem[];
    float4* sF   = smem;                      // slab: becomes A_i after fold
    float4* sX   = sF + SLAB_F4;              // slab: becomes B_i after fold
    float4* sA   = sX + SLAB_F4;              // [SUBS][TILE_C4] scan
    float4* sB   = sA + SUBS * TILE_C4;
    float4* sHin = sB + SUBS * TILE_C4;       // [TILE_C4]

    const int tid  = threadIdx.x;
    const int c    = tid & (TILE_C4 - 1);       // f4 channel within tile
    const int s    = tid >> 4;                  // sub-chunk index (0..15)
    const int tile = blockIdx.x >> 5;           // / TBLKS
    const int tblk = blockIdx.x & (TBLKS - 1);  // fastest-varying in bid

    const int cg = tile * TILE_C4 + c;
    const int t0 = tblk * TB + s * SL;

    const float4* fp = f + (size_t)t0 * C4 + cg;
    const float4* xp = x + (size_t)t0 * C4 + cg;

    // Per-thread slab slots (row = s*SL + i, col = c).
    const int slot0 = (s * SL) * TILE_C4 + c;
    const uint32_t sF_u = (uint32_t)__cvta_generic_to_shared(sF + slot0);
    const uint32_t sX_u = (uint32_t)__cvta_generic_to_shared(sX + slot0);

    // ---- Phase 0: issue fills as per-timestep groups (f_i, x_i) ----
#pragma unroll
    for (int i = 0; i < SL; i++) {
        cp_async16(sF_u + (uint32_t)(i * TILE_C4) * 16u, fp + (size_t)i * C4);
        cp_async16(sX_u + (uint32_t)(i * TILE_C4) * 16u, xp + (size_t)i * C4);
        asm volatile("cp.async.commit_group;" ::: "memory");
    }

    // ---- Phase 1: fold inclusive prefix as groups land; overwrite slab ----
    float4 cA, cB;
#pragma unroll
    for (int i = 0; i < SL; i++) {
        cp_async_wait<SL - 1>();   // adjusted below by unrolled specialization
        // NOTE: wait target must shrink with i; do it explicitly:
        switch (i) {   // compile-time resolved under full unroll
            case 0: cp_async_wait<SL - 1>(); break;
            case 1: cp_async_wait<SL - 2>(); break;
            case 2: cp_async_wait<SL - 3>(); break;
            case 3: cp_async_wait<SL - 4>(); break;
            case 4: cp_async_wait<SL - 5>(); break;
            case 5: cp_async_wait<SL - 6>(); break;
            case 6: cp_async_wait<SL - 7>(); break;
            default: cp_async_wait<0>(); break;
        }
        float4 ft = sF[slot0 + i * TILE_C4];
        float4 xt = sX[slot0 + i * TILE_C4];
        float4 a = make_float4(1.f - ft.x, 1.f - ft.y, 1.f - ft.z, 1.f - ft.w);
        float4 b = f4_mul(ft, xt);
        if (i == 0) { cA = a; cB = b; }
        else {
            cB = f4_fma(a, cB, b);        // B_i = a_i*B_{i-1} + b_i
            cA = f4_mul(a, cA);           // A_i = a_i*A_{i-1}
        }
        sF[slot0 + i * TILE_C4] = cA;     // in-place: slab now holds prefix
        sX[slot0 + i * TILE_C4] = cB;
    }

    // ---- Phase 2: Hillis-Steele over the 16 sub-chunks ----
    sA[s * TILE_C4 + c] = cA;
    sB[s * TILE_C4 + c] = cB;
    __syncthreads();
#pragma unroll
    for (int d = 1; d < SUBS; d <<= 1) {
        float4 pA, pB;
        if (s >= d) {
            pA = sA[(s - d) * TILE_C4 + c];
            pB = sB[(s - d) * TILE_C4 + c];
        }
        __syncthreads();
        if (s >= d) {
            cB = f4_fma(cA, pB, cB);   // cur ∘ prev
            cA = f4_mul(cA, pA);
            sA[s * TILE_C4 + c] = cA;
            sB[s * TILE_C4 + c] = cB;
        }
        __syncthreads();
    }
    float4 exA = make_float4(1.f, 1.f, 1.f, 1.f);
    float4 exB = make_float4(0.f, 0.f, 0.f, 0.f);
    if (s > 0) {
        exA = sA[(s - 1) * TILE_C4 + c];
        exB = sB[(s - 1) * TILE_C4 + c];
    }

    // ---- Phase 3: look-back; warp 0 lane-parallel wait (tblk <= 31) ----
    if (tid < 32) {
        const int lane = tid;
        float4 blkA, blkB;
        int cg0 = 0;
        if (lane < TILE_C4) {
            blkA = sA[(SUBS - 1) * TILE_C4 + lane];
            blkB = sB[(SUBS - 1) * TILE_C4 + lane];
            cg0  = tile * TILE_C4 + lane;
        }
        const int fbase = tile * TBLKS;
        if (tblk == 0) {
            if (lane < TILE_C4) {
                float4 hin0 = h0[cg0];
                g_prefH[cg0] = f4_fma(blkA, hin0, blkB);
                sHin[lane] = hin0;
            }
            __syncwarp(0xFFFFFFFFu);
            if (lane == 0)
                st_release_gpu(&g_flag[fbase + 0], 2);
        } else {
            if (lane < TILE_C4) {
                g_aggA[(size_t)tblk * C4 + cg0] = blkA;
                g_aggB[(size_t)tblk * C4 + cg0] = blkB;
            }
            __syncwarp(0xFFFFFFFFu);
            if (lane == 0)
                st_release_gpu(&g_flag[fbase + tblk], 1);

            // Parallel wait: lane j polls predecessor j; ballot collapses all
            // polls into ~1 L2 round-trip per retry.
            {
                const int need = (lane == 0) ? 2 : 1;
                bool ok;
                do {
                    ok = (lane >= tblk) ||
                         (ld_acquire_gpu(&g_flag[fbase + lane]) >= need);
                } while (!__all_sync(0xFFFFFFFFu, ok));
            }
            __syncwarp(0xFFFFFFFFu);   // order acquires before cross-lane reads

            if (lane < TILE_C4) {
                float4 accA = make_float4(1.f, 1.f, 1.f, 1.f);
                float4 accB = make_float4(0.f, 0.f, 0.f, 0.f);
#pragma unroll 4
                for (int j = tblk - 1; j >= 1; j--) {
                    float4 aj = g_aggA[(size_t)j * C4 + cg0];
                    float4 bj = g_aggB[(size_t)j * C4 + cg0];
                    accB = f4_fma(accA, bj, accB);
                    accA = f4_mul(accA, aj);
                }
                float4 hpre = g_prefH[cg0];
                sHin[lane] = f4_fma(accA, hpre, accB);
            }
        }
    }
    __syncthreads();

    // ---- Phase 4: LDS prefix -> fma -> STG (no global re-read) ----
    const float4 hsub = f4_fma(exA, sHin[c], exB);  // h entering sub-chunk
    float4* op = out + (size_t)t0 * C4 + cg;
#pragma unroll
    for (int i = 0; i < SL; i++) {
        float4 Ai = sF[slot0 + i * TILE_C4];
        float4 Bi = sX[slot0 + i * TILE_C4];
        float4 h = f4_fma(Ai, hsub, Bi);            // independent per i
        __stcs(op + (size_t)i * C4, h);
    }
}

extern "C" void kernel_launch(void* const* d_in, const int* in_sizes, int n_in,
                              void* d_out, int out_size)
{
    const float4* f  = (const float4*)d_in[0];
    const float4* x  = (const float4*)d_in[1];
    const float4* h0 = (const float4*)d_in[2];
    float4* out = (float4*)d_out;

    static bool attr_set = false;
    if (!attr_set) {
        cudaFuncSetAttribute(forget_mult_v14_kernel,
                             cudaFuncAttributeMaxDynamicSharedMemorySize,
                             SMEM_BYTES);
        attr_set = true;
    }

    reset_flags_kernel<<<(TILES * TBLKS + 255) / 256, 256>>>();

    dim3 grid(TILES * TBLKS);   // tblk fastest -> predecessors at lower bid
    dim3 block(NTHREADS);
    forget_mult_v14_kernel<<<grid, block, SMEM_BYTES>>>(f, x, h0, out);
}